// round 12
// baseline (speedup 1.0000x reference)
#include <cuda_runtime.h>
#include <cuda_fp16.h>
#include <cstdint>

// Problem constants: B=4, N=1024, C=16, H=W=128
#define BB 4
#define NN 1024
#define CC 16
#define HW 128

// f16 separable factors: ev [b][gv][n], euT [b][gu][n] (gu-major)
__device__ unsigned short g_ev [BB * HW * NN];
__device__ unsigned short g_euT[BB * HW * NN];
// partial sums from the n-high half (4MB)
__device__ float g_part[BB * CC * HW * HW];

__device__ __forceinline__ float ex2f(float x) {
    float y;
    asm("ex2.approx.ftz.f32 %0, %1;" : "=f"(y) : "f"(x));
    return y;
}

__device__ __forceinline__ uint32_t smem_u32(const void* p) {
    uint32_t a;
    asm("{ .reg .u64 t; cvta.to.shared.u64 t, %1; cvt.u32.u64 %0, t; }"
        : "=r"(a) : "l"(p));
    return a;
}

__device__ __forceinline__ uint32_t hmul2(uint32_t a, uint32_t b) {
    uint32_t d;
    asm("mul.rn.f16x2 %0, %1, %2;" : "=r"(d) : "r"(a), "r"(b));
    return d;
}

__device__ __forceinline__ void ldsm_x4(uint32_t* r, uint32_t addr) {
    asm volatile("ldmatrix.sync.aligned.m8n8.x4.shared.b16 {%0,%1,%2,%3}, [%4];"
                 : "=r"(r[0]), "=r"(r[1]), "=r"(r[2]), "=r"(r[3]) : "r"(addr));
}

__device__ __forceinline__ void mma16816(float* d, const uint32_t* a,
                                         const uint32_t* b) {
    asm volatile(
        "mma.sync.aligned.m16n8k16.row.col.f32.f16.f16.f32 "
        "{%0,%1,%2,%3}, {%4,%5,%6,%7}, {%8,%9}, {%0,%1,%2,%3};"
        : "+f"(d[0]), "+f"(d[1]), "+f"(d[2]), "+f"(d[3])
        : "r"(a[0]), "r"(a[1]), "r"(a[2]), "r"(a[3]), "r"(b[0]), "r"(b[1]));
}

// ---------------------------------------------------------------------------
// Kernel A: project points, write f16 separable factors (unchanged).
// ---------------------------------------------------------------------------
__global__ void __launch_bounds__(128) proj_kernel(
    const float* __restrict__ Kc,
    const float* __restrict__ RT,
    const float* __restrict__ pts3d,
    const float* __restrict__ scale)
{
    const int b  = blockIdx.x >> 5;
    const int n0 = (blockIdx.x & 31) << 5;
    const int tid = threadIdx.x;

    __shared__ float su[32], sv[32], sinv[32], smask[32];

    if (tid < 32) {
        const int n = n0 + tid;
        const float* rt = RT + b * 12;
        const float* p  = pts3d + (b * NN + n) * 3;
        float p0 = p[0], p1 = p[1], p2 = p[2];
        float l0 = rt[0] * p0 + rt[1] * p1 + rt[2]  * p2 + rt[3];
        float l1 = rt[4] * p0 + rt[5] * p1 + rt[6]  * p2 + rt[7];
        float l2 = rt[8] * p0 + rt[9] * p1 + rt[10] * p2 + rt[11];
        float x = Kc[0] * l0 + Kc[1] * l1 + Kc[2] * l2;
        float y = Kc[3] * l0 + Kc[4] * l1 + Kc[5] * l2;
        float z = Kc[6] * l0 + Kc[7] * l1 + Kc[8] * l2;
        float mask = (z > 0.1f) ? 1.0f : 0.0f;
        float zc = fmaxf(z, 0.1f);
        float sig = Kc[0] * 0.03125f;            // sigma = K[0,0]/32
        float inv = 1.0f / (scale[b * NN + n] * sig * sig);
        su[tid]   = x / zc;
        sv[tid]   = y / zc;
        sinv[tid] = -1.4426950408889634f * inv;  // fold -log2(e)
        smask[tid] = mask;
    }
    __syncthreads();

    const int warp = tid >> 5;
    const int lane = tid & 31;

    {
        const float v  = sv[lane];
        const float ni = sinv[lane];
        unsigned short* dst = g_ev + (size_t)(b * HW) * NN + n0 + lane;
        #pragma unroll 8
        for (int j = 0; j < 32; j++) {
            const int gv = warp * 32 + j;
            float d = v - (float)gv;
            __half h = __float2half(ex2f(d * d * ni));
            dst[(size_t)gv * NN] = __half_as_ushort(h);
        }
    }
    {
        const int i = lane;
        const float u  = su[i];
        const float ni = sinv[i];
        const float m  = smask[i];
        unsigned short* dst = g_euT + (size_t)(b * HW) * NN + n0 + i;
        #pragma unroll 8
        for (int j = 0; j < 32; j++) {
            const int gu = warp * 32 + j;
            float d = u - (float)gu;
            __half h = __float2half(ex2f(d * d * ni) * m);
            dst[(size_t)gu * NN] = __half_as_ushort(h);
        }
    }
}

// ---------------------------------------------------------------------------
// Kernel B: HMMA GEMM, n-SPLIT: grid 256 = (b, 4 gv rows, n-half).
// Per-warp instruction mix identical to R9/R11; 8 chunks of 64 n per CTA.
// smem 57.6KB -> 2 CTAs co-reside per SM (8 warps/SMSP) to hide dep latency.
// nh=0 writes out; nh=1 writes g_part; combine_kernel adds them.
// ---------------------------------------------------------------------------
#define EU_STRIDE 72                       // halfwords per padded eu row
#define FT_STRIDE 520                      // halfwords per padded ft row (512+8)
#define SEU_OFF   0u                       // 2 x 128 x 72 x 2B = 36864
#define SFT_OFF   36864u                   // 16 x 520 x 2B    = 16640
#define SEV_OFF   53504u                   // 4 x 512 x 2B     =  4096
#define SMEM_DYN  57600u

__global__ void __launch_bounds__(512, 2) accum_kernel(
    const float* __restrict__ feat,
    float* __restrict__ out)
{
    extern __shared__ __align__(16) char smem[];
    unsigned short* sft = (unsigned short*)(smem + SFT_OFF);  // [16][520]
    unsigned short* sev = (unsigned short*)(smem + SEV_OFF);  // [4][512]

    const int nh  = blockIdx.x & 1;
    const int gv0 = ((blockIdx.x >> 1) & 31) << 2;
    const int b   = blockIdx.x >> 6;
    const int nbase = nh << 9;              // 0 or 512
    const int t    = threadIdx.x;
    const int wid  = t >> 5;
    const int lane = t & 31;

    // ---- stage featT half (f32 -> f16), padded stride 520 ----
    {
        const int c  = t & 15;
        const int nv = t >> 4;
        const float* fb = feat + ((size_t)b * NN + nbase) * CC;
        #pragma unroll 8
        for (int i = 0; i < 16; i++) {
            const int n = nv + 32 * i;
            sft[c * FT_STRIDE + n] =
                __half_as_ushort(__float2half(fb[(size_t)n * CC + c]));
        }
    }
    // ---- stage ev rows half (f16 copy, 8B/thread) ----
    {
        const int r  = t >> 7;
        const int i4 = (t & 127) * 4;
        *(uint2*)&sev[r * 512 + i4] =
            *(const uint2*)(g_ev + (size_t)(b * HW + gv0 + r) * NN + nbase + i4);
    }

    // eu staging mapping: 4 threads per gu row, 16 halfwords (32B) each
    const int srow = t >> 2;
    const int sq   = (t & 3) * 16;
    const unsigned short* esrc =
        g_euT + (size_t)(b * HW + srow) * NN + nbase + sq;
    unsigned short* edst = (unsigned short*)(smem + SEU_OFF) + srow * EU_STRIDE + sq;

    {
        const uint4 p0 = *(const uint4*)esrc;
        const uint4 p1 = *(const uint4*)(esrc + 8);
        *(uint4*)edst       = p0;
        *(uint4*)(edst + 8) = p1;
    }
    __syncthreads();

    // consumer mapping
    const int mt = wid & 7;
    const int rp = wid >> 3;
    const int c0 = (lane & 3) * 2;

    const unsigned short* evr0 = sev + (rp * 2) * 512;
    const unsigned short* evr1 = evr0 + 512;

    const uint32_t sbase = smem_u32(smem);
    const uint32_t euLm0 = sbase + SEU_OFF +
        (uint32_t)(((mt * 16 + (lane & 15)) * EU_STRIDE + (lane >> 4) * 8) * 2);
    const uint32_t ftLm0 = sbase + SFT_OFF +
        (uint32_t)((((lane & 15)) * FT_STRIDE + (lane >> 4) * 8) * 2);

    float acc[2][2][4];
    #pragma unroll
    for (int rr = 0; rr < 2; rr++)
        #pragma unroll
        for (int nt = 0; nt < 2; nt++)
            #pragma unroll
            for (int q = 0; q < 4; q++) acc[rr][nt][q] = 0.0f;

    #pragma unroll 1
    for (int k = 0; k < 8; k++) {
        const int nb = k * 64;
        // prefetch next eu chunk (coalesced LDG.128)
        uint4 p0, p1;
        if (k < 7) {
            const unsigned short* s = esrc + (size_t)(nb + 64);
            p0 = *(const uint4*)s;
            p1 = *(const uint4*)(s + 8);
        }

        const uint32_t euLm = euLm0 + (uint32_t)(k & 1) * (128 * EU_STRIDE * 2);
        const uint32_t ftLm = ftLm0 + (uint32_t)(nb * 2);

        #pragma unroll
        for (int ks = 0; ks < 4; ks++) {
            const int nA = nb + ks * 16 + c0;
            const int nB = nA + 8;

            const uint32_t e0A = *(const uint32_t*)(evr0 + nA);
            const uint32_t e0B = *(const uint32_t*)(evr0 + nB);
            const uint32_t e1A = *(const uint32_t*)(evr1 + nA);
            const uint32_t e1B = *(const uint32_t*)(evr1 + nB);

            uint32_t u[4];
            ldsm_x4(u, euLm + (uint32_t)(ks * 32));

            uint32_t f[4];
            ldsm_x4(f, ftLm + (uint32_t)(ks * 32));
            uint32_t bf0[2] = { f[0], f[2] };
            uint32_t bf1[2] = { f[1], f[3] };

            uint32_t a0[4] = { hmul2(e0A, u[0]), hmul2(e0A, u[1]),
                               hmul2(e0B, u[2]), hmul2(e0B, u[3]) };
            mma16816(acc[0][0], a0, bf0);
            mma16816(acc[0][1], a0, bf1);

            uint32_t a1[4] = { hmul2(e1A, u[0]), hmul2(e1A, u[1]),
                               hmul2(e1B, u[2]), hmul2(e1B, u[3]) };
            mma16816(acc[1][0], a1, bf0);
            mma16816(acc[1][1], a1, bf1);
        }

        if (k < 7) {
            unsigned short* d = edst + ((k + 1) & 1) * (128 * EU_STRIDE);
            *(uint4*)d       = p0;
            *(uint4*)(d + 8) = p1;
        }
        __syncthreads();
    }

    // ---- epilogue: D[gu][c] -> (out | g_part)[b][c][gv][gu] ----
    {
        float* base = nh ? g_part : out;
        const int guw = mt * 16 + (lane >> 2);
        const int c0w = (lane & 3) * 2;
        #pragma unroll
        for (int rr = 0; rr < 2; rr++) {
            const int gv = gv0 + rp * 2 + rr;
            float* ob = base + (size_t)b * CC * HW * HW + (size_t)gv * HW;
            #pragma unroll
            for (int nt = 0; nt < 2; nt++) {
                const int c = nt * 8 + c0w;
                ob[(size_t)c * HW * HW + guw]           = acc[rr][nt][0];
                ob[(size_t)(c + 1) * HW * HW + guw]     = acc[rr][nt][1];
                ob[(size_t)c * HW * HW + guw + 8]       = acc[rr][nt][2];
                ob[(size_t)(c + 1) * HW * HW + guw + 8] = acc[rr][nt][3];
            }
        }
    }
}

// ---------------------------------------------------------------------------
// Kernel C: out += g_part  (L2-resident, float4)
// ---------------------------------------------------------------------------
__global__ void __launch_bounds__(512) combine_kernel(float* __restrict__ out)
{
    const int i = blockIdx.x * 512 + threadIdx.x;
    float4* o = (float4*)out;
    const float4* p = (const float4*)g_part;
    float4 a = o[i];
    const float4 q = p[i];
    a.x += q.x; a.y += q.y; a.z += q.z; a.w += q.w;
    o[i] = a;
}

extern "C" void kernel_launch(void* const* d_in, const int* in_sizes, int n_in,
                              void* d_out, int out_size)
{
    const float* Kc    = (const float*)d_in[0];
    const float* RT    = (const float*)d_in[1];
    const float* pts3d = (const float*)d_in[2];
    const float* feat  = (const float*)d_in[3];
    const float* scale = (const float*)d_in[4];
    float* out = (float*)d_out;

    cudaFuncSetAttribute(accum_kernel,
                         cudaFuncAttributeMaxDynamicSharedMemorySize, SMEM_DYN);

    proj_kernel<<<BB * NN / 32, 128>>>(Kc, RT, pts3d, scale);
    accum_kernel<<<BB * 64, 512, SMEM_DYN>>>(feat, out);
    combine_kernel<<<(BB * CC * HW * HW / 4) / 512, 512>>>(out);
}

// round 13
// speedup vs baseline: 1.7690x; 1.7690x over previous
#include <cuda_runtime.h>
#include <cuda_fp16.h>
#include <cstdint>

// Problem constants: B=4, N=1024, C=16, H=W=128
#define BB 4
#define NN 1024
#define CC 16
#define HW 128

// f16 separable factors over COMPACT slots: ev [b][gv][slot], euT [b][gu][slot]
__device__ unsigned short g_ev [BB * HW * NN];
__device__ unsigned short g_euT[BB * HW * NN];
// compact point data
__device__ float g_pu[BB * NN], g_pv[BB * NN], g_ps[BB * NN];
__device__ int   g_pidx[BB * NN];
__device__ int   g_cnt[BB];

__device__ __forceinline__ float ex2f(float x) {
    float y;
    asm("ex2.approx.ftz.f32 %0, %1;" : "=f"(y) : "f"(x));
    return y;
}

__device__ __forceinline__ uint32_t smem_u32(const void* p) {
    uint32_t a;
    asm("{ .reg .u64 t; cvta.to.shared.u64 t, %1; cvt.u32.u64 %0, t; }"
        : "=r"(a) : "l"(p));
    return a;
}

__device__ __forceinline__ uint32_t hmul2(uint32_t a, uint32_t b) {
    uint32_t d;
    asm("mul.rn.f16x2 %0, %1, %2;" : "=r"(d) : "r"(a), "r"(b));
    return d;
}

__device__ __forceinline__ void ldsm_x4(uint32_t* r, uint32_t addr) {
    asm volatile("ldmatrix.sync.aligned.m8n8.x4.shared.b16 {%0,%1,%2,%3}, [%4];"
                 : "=r"(r[0]), "=r"(r[1]), "=r"(r[2]), "=r"(r[3]) : "r"(addr));
}

__device__ __forceinline__ void mma16816(float* d, const uint32_t* a,
                                         const uint32_t* b) {
    asm volatile(
        "mma.sync.aligned.m16n8k16.row.col.f32.f16.f16.f32 "
        "{%0,%1,%2,%3}, {%4,%5,%6,%7}, {%8,%9}, {%0,%1,%2,%3};"
        : "+f"(d[0]), "+f"(d[1]), "+f"(d[2]), "+f"(d[3])
        : "r"(a[0]), "r"(a[1]), "r"(a[2]), "r"(a[3]), "r"(b[0]), "r"(b[1]));
}

// ---------------------------------------------------------------------------
// Kernel P1: project all points, keep survivors (nonzero f16 weight possible),
// deterministic ballot/prefix-scan compaction. grid = BB blocks x 1024 thr.
// ---------------------------------------------------------------------------
__global__ void __launch_bounds__(1024) compact_kernel(
    const float* __restrict__ Kc,
    const float* __restrict__ RT,
    const float* __restrict__ pts3d,
    const float* __restrict__ scale)
{
    const int b = blockIdx.x;
    const int n = threadIdx.x;
    const int wid = n >> 5, lane = n & 31;

    const float* rt = RT + b * 12;
    const float* p  = pts3d + (size_t)(b * NN + n) * 3;
    float p0 = p[0], p1 = p[1], p2 = p[2];
    float l0 = rt[0] * p0 + rt[1] * p1 + rt[2]  * p2 + rt[3];
    float l1 = rt[4] * p0 + rt[5] * p1 + rt[6]  * p2 + rt[7];
    float l2 = rt[8] * p0 + rt[9] * p1 + rt[10] * p2 + rt[11];
    float x = Kc[0] * l0 + Kc[1] * l1 + Kc[2] * l2;
    float y = Kc[3] * l0 + Kc[4] * l1 + Kc[5] * l2;
    float z = Kc[6] * l0 + Kc[7] * l1 + Kc[8] * l2;
    float zc = fmaxf(z, 0.1f);
    float u = x / zc, v = y / zc;
    float sig = Kc[0] * 0.03125f;                 // sigma = K[0,0]/32
    float s = scale[b * NN + n] * sig * sig;      // s <= 16
    float t = sqrtf(17.5f * s);                   // f16-exact-zero radius

    // survivor iff weight can be a nonzero f16 anywhere on the 128x128 grid
    bool keep = (z > 0.1f) && (u > -t) && (u < 127.0f + t)
                           && (v > -t) && (v < 127.0f + t);

    __shared__ int wtot[32];
    unsigned bal = __ballot_sync(0xffffffffu, keep);
    int pre = __popc(bal & ((1u << lane) - 1));
    if (lane == 0) wtot[wid] = __popc(bal);
    __syncthreads();
    if (wid == 0) {
        int vtot = wtot[lane], xs = vtot;
        #pragma unroll
        for (int o = 1; o < 32; o <<= 1) {
            int yv = __shfl_up_sync(0xffffffffu, xs, o);
            if (lane >= o) xs += yv;
        }
        wtot[lane] = xs - vtot;                   // exclusive
        if (lane == 31) g_cnt[b] = xs;            // total
    }
    __syncthreads();
    if (keep) {
        const int slot = wtot[wid] + pre;
        g_pu[b * NN + slot]   = u;
        g_pv[b * NN + slot]   = v;
        g_ps[b * NN + slot]   = -1.4426950408889634f / s;  // -log2(e)/s
        g_pidx[b * NN + slot] = n;
    }
}

// ---------------------------------------------------------------------------
// Kernel P2: write f16 ev/euT for compact slots; zero-fill pad to 64 boundary.
// grid = BB*32 blocks x 128 threads; block = 32 slots. Early-exit past pad.
// ---------------------------------------------------------------------------
__global__ void __launch_bounds__(128) proj_kernel(void)
{
    const int b  = blockIdx.x >> 5;
    const int s0 = (blockIdx.x & 31) << 5;
    const int cnt = g_cnt[b];
    const int pad = (cnt + 63) & ~63;
    if (s0 >= pad) return;

    const int tid = threadIdx.x;
    __shared__ float su[32], sv[32], sinv[32], smask[32];

    if (tid < 32) {
        const int slot = s0 + tid;
        if (slot < cnt) {
            su[tid] = g_pu[b * NN + slot];
            sv[tid] = g_pv[b * NN + slot];
            sinv[tid] = g_ps[b * NN + slot];
            smask[tid] = 1.0f;
        } else {
            su[tid] = 0.f; sv[tid] = 0.f; sinv[tid] = 0.f; smask[tid] = 0.f;
        }
    }
    __syncthreads();

    const int warp = tid >> 5;
    const int lane = tid & 31;

    // ev[b][gv][s0+lane]
    {
        const float v  = sv[lane];
        const float ni = sinv[lane];
        const float m  = smask[lane];
        unsigned short* dst = g_ev + (size_t)(b * HW) * NN + s0 + lane;
        #pragma unroll 8
        for (int j = 0; j < 32; j++) {
            const int gv = warp * 32 + j;
            float d = v - (float)gv;
            __half h = __float2half(ex2f(d * d * ni) * m);
            dst[(size_t)gv * NN] = __half_as_ushort(h);
        }
    }
    // euT[b][gu][s0+lane]
    {
        const float u  = su[lane];
        const float ni = sinv[lane];
        const float m  = smask[lane];
        unsigned short* dst = g_euT + (size_t)(b * HW) * NN + s0 + lane;
        #pragma unroll 8
        for (int j = 0; j < 32; j++) {
            const int gu = warp * 32 + j;
            float d = u - (float)gu;
            __half h = __float2half(ex2f(d * d * ni) * m);
            dst[(size_t)gu * NN] = __half_as_ushort(h);
        }
    }
}

// ---------------------------------------------------------------------------
// Kernel B: HMMA GEMM over COMPACT K (nch chunks of 64 survivors).
// Structure identical to R11 (ldmatrix fragments, register-built A).
// ---------------------------------------------------------------------------
#define EU_STRIDE 72
#define FT_STRIDE 1032
#define SEU_OFF   0u                       // 2 x 128 x 72 x 2B = 36864
#define SFT_OFF   36864u                   // 16 x 1032 x 2B   = 33024
#define SEV_OFF   69888u                   // 4 x 1024 x 2B    =  8192
#define SMEM_DYN  78592u

__global__ void __launch_bounds__(512, 1) accum_kernel(
    const float* __restrict__ feat,
    float* __restrict__ out)
{
    extern __shared__ __align__(16) char smem[];
    unsigned short* sft = (unsigned short*)(smem + SFT_OFF);
    unsigned short* sev = (unsigned short*)(smem + SEV_OFF);

    const int b   = blockIdx.x >> 5;
    const int gv0 = (blockIdx.x & 31) << 2;
    const int t    = threadIdx.x;
    const int wid  = t >> 5;
    const int lane = t & 31;

    const int cnt = g_cnt[b];
    const int pad = (cnt + 63) & ~63;
    const int nch = pad >> 6;

    // ---- stage featT via idx gather (zeros for pad slots) ----
    {
        const int c = t & 15;
        for (int s = t >> 4; s < pad; s += 32) {
            float v = 0.0f;
            if (s < cnt)
                v = feat[((size_t)b * NN + g_pidx[b * NN + s]) * CC + c];
            sft[c * FT_STRIDE + s] = __half_as_ushort(__float2half(v));
        }
    }
    // ---- stage ev rows (pads already zero in gmem) ----
    {
        const int r  = t >> 7;
        const int i8 = (t & 127) * 8;
        if (i8 < pad)
            *(uint4*)&sev[r * 1024 + i8] =
                *(const uint4*)(g_ev + (size_t)(b * HW + gv0 + r) * NN + i8);
    }

    // eu staging mapping: 4 threads per gu row, 16 halfwords (32B) each
    const int srow = t >> 2;
    const int sq   = (t & 3) * 16;
    const unsigned short* esrc = g_euT + (size_t)(b * HW + srow) * NN + sq;
    unsigned short* edst =
        (unsigned short*)(smem + SEU_OFF) + srow * EU_STRIDE + sq;

    if (nch > 0) {
        const uint4 p0 = *(const uint4*)esrc;
        const uint4 p1 = *(const uint4*)(esrc + 8);
        *(uint4*)edst       = p0;
        *(uint4*)(edst + 8) = p1;
    }
    __syncthreads();

    // consumer mapping
    const int mt = wid & 7;
    const int rp = wid >> 3;
    const int c0 = (lane & 3) * 2;

    const unsigned short* evr0 = sev + (rp * 2) * 1024;
    const unsigned short* evr1 = evr0 + 1024;

    const uint32_t sbase = smem_u32(smem);
    const uint32_t euLm0 = sbase + SEU_OFF +
        (uint32_t)(((mt * 16 + (lane & 15)) * EU_STRIDE + (lane >> 4) * 8) * 2);
    const uint32_t ftLm0 = sbase + SFT_OFF +
        (uint32_t)((((lane & 15)) * FT_STRIDE + (lane >> 4) * 8) * 2);

    float acc[2][2][4];
    #pragma unroll
    for (int rr = 0; rr < 2; rr++)
        #pragma unroll
        for (int nt = 0; nt < 2; nt++)
            #pragma unroll
            for (int q = 0; q < 4; q++) acc[rr][nt][q] = 0.0f;

    #pragma unroll 1
    for (int k = 0; k < nch; k++) {
        const int nb = k * 64;
        uint4 p0, p1;
        if (k + 1 < nch) {
            const unsigned short* s = esrc + (size_t)(nb + 64);
            p0 = *(const uint4*)s;
            p1 = *(const uint4*)(s + 8);
        }

        const uint32_t euLm = euLm0 + (uint32_t)(k & 1) * (128 * EU_STRIDE * 2);
        const uint32_t ftLm = ftLm0 + (uint32_t)(nb * 2);

        #pragma unroll
        for (int ks = 0; ks < 4; ks++) {
            const int nA = nb + ks * 16 + c0;
            const int nB = nA + 8;

            const uint32_t e0A = *(const uint32_t*)(evr0 + nA);
            const uint32_t e0B = *(const uint32_t*)(evr0 + nB);
            const uint32_t e1A = *(const uint32_t*)(evr1 + nA);
            const uint32_t e1B = *(const uint32_t*)(evr1 + nB);

            uint32_t u[4];
            ldsm_x4(u, euLm + (uint32_t)(ks * 32));

            uint32_t f[4];
            ldsm_x4(f, ftLm + (uint32_t)(ks * 32));
            uint32_t bf0[2] = { f[0], f[2] };
            uint32_t bf1[2] = { f[1], f[3] };

            uint32_t a0[4] = { hmul2(e0A, u[0]), hmul2(e0A, u[1]),
                               hmul2(e0B, u[2]), hmul2(e0B, u[3]) };
            mma16816(acc[0][0], a0, bf0);
            mma16816(acc[0][1], a0, bf1);

            uint32_t a1[4] = { hmul2(e1A, u[0]), hmul2(e1A, u[1]),
                               hmul2(e1B, u[2]), hmul2(e1B, u[3]) };
            mma16816(acc[1][0], a1, bf0);
            mma16816(acc[1][1], a1, bf1);
        }

        if (k + 1 < nch) {
            unsigned short* d = edst + ((k + 1) & 1) * (128 * EU_STRIDE);
            *(uint4*)d       = p0;
            *(uint4*)(d + 8) = p1;
        }
        __syncthreads();
    }

    // ---- epilogue: D[gu][c] -> out[b][c][gv][gu] ----
    {
        const int guw = mt * 16 + (lane >> 2);
        const int c0w = (lane & 3) * 2;
        #pragma unroll
        for (int rr = 0; rr < 2; rr++) {
            const int gv = gv0 + rp * 2 + rr;
            float* ob = out + (size_t)b * CC * HW * HW + (size_t)gv * HW;
            #pragma unroll
            for (int nt = 0; nt < 2; nt++) {
                const int c = nt * 8 + c0w;
                ob[(size_t)c * HW * HW + guw]           = acc[rr][nt][0];
                ob[(size_t)(c + 1) * HW * HW + guw]     = acc[rr][nt][1];
                ob[(size_t)c * HW * HW + guw + 8]       = acc[rr][nt][2];
                ob[(size_t)(c + 1) * HW * HW + guw + 8] = acc[rr][nt][3];
            }
        }
    }
}

extern "C" void kernel_launch(void* const* d_in, const int* in_sizes, int n_in,
                              void* d_out, int out_size)
{
    const float* Kc    = (const float*)d_in[0];
    const float* RT    = (const float*)d_in[1];
    const float* pts3d = (const float*)d_in[2];
    const float* feat  = (const float*)d_in[3];
    const float* scale = (const float*)d_in[4];
    float* out = (float*)d_out;

    cudaFuncSetAttribute(accum_kernel,
                         cudaFuncAttributeMaxDynamicSharedMemorySize, SMEM_DYN);

    compact_kernel<<<BB, 1024>>>(Kc, RT, pts3d, scale);
    proj_kernel<<<BB * 32, 128>>>();
    accum_kernel<<<BB * 32, 512, SMEM_DYN>>>(feat, out);
}